// round 9
// baseline (speedup 1.0000x reference)
#include <cuda_runtime.h>
#include <cuda_bf16.h>
#include <cstdint>

#define NB 64
#define UD 512
#define VD 32000
#define TS 20
#define ZN 2048
#define GK 1024

// ---------------- persistent device scratch ----------------
__device__ float g_h[NB * UD];
__device__ float g_c[NB * UD];
__device__ float g_zpart[8][NB * ZN];
__device__ unsigned long long g_amax[NB];
__device__ unsigned int g_barrier;   // monotonic ticket barrier (64/launch)
__device__ __nv_bfloat16 g_Wd0[(size_t)UD * VD];
__device__ __nv_bfloat16 g_Wd1[(size_t)UD * VD];
__device__ __nv_bfloat16 g_Wg0[(size_t)GK * ZN];
__device__ __nv_bfloat16 g_Wg1[(size_t)GK * ZN];
__device__ __nv_bfloat16 g_Al0[NB * UD];
__device__ __nv_bfloat16 g_Al1[NB * UD];

// ---------------- helpers ----------------
__device__ __forceinline__ unsigned long long enc_max(float v, int col) {
    unsigned int u = __float_as_uint(v);
    unsigned int key = (u & 0x80000000u) ? ~u : (u | 0x80000000u);
    return ((unsigned long long)key << 32) |
           (unsigned long long)(0xFFFFFFFFu - (unsigned int)col);
}
__device__ __forceinline__ int dec_idx(unsigned long long e) {
    return (int)(0xFFFFFFFFu - (unsigned int)(e & 0xFFFFFFFFull));
}
__device__ __forceinline__ void split2(float v, __nv_bfloat16& b0, __nv_bfloat16& b1) {
    b0 = __float2bfloat16(v);
    b1 = __float2bfloat16(v - __bfloat162float(b0));
}
__device__ __forceinline__ uint32_t smem_u32(const void* p) {
    uint32_t a;
    asm("{ .reg .u64 t; cvta.to.shared.u64 t, %1; cvt.u32.u64 %0, t; }"
        : "=r"(a) : "l"(p));
    return a;
}
__device__ __forceinline__ void cp16(uint32_t dst, const void* src) {
    asm volatile("cp.async.cg.shared.global [%0], [%1], 16;" :: "r"(dst), "l"(src));
}
#define CP_COMMIT() asm volatile("cp.async.commit_group;" ::: "memory")
#define CP_WAIT(n)  asm volatile("cp.async.wait_group %0;" :: "n"(n) : "memory")

__device__ __forceinline__ void ldm_x4(uint32_t* r, uint32_t addr) {
    asm volatile("ldmatrix.sync.aligned.m8n8.x4.shared.b16 {%0,%1,%2,%3}, [%4];"
        : "=r"(r[0]), "=r"(r[1]), "=r"(r[2]), "=r"(r[3]) : "r"(addr));
}
__device__ __forceinline__ void ldm_x4t(uint32_t* r, uint32_t addr) {
    asm volatile("ldmatrix.sync.aligned.m8n8.x4.trans.shared.b16 {%0,%1,%2,%3}, [%4];"
        : "=r"(r[0]), "=r"(r[1]), "=r"(r[2]), "=r"(r[3]) : "r"(addr));
}
__device__ __forceinline__ void mma16816(float* c, const uint32_t* a, const uint32_t* b) {
    asm volatile(
        "mma.sync.aligned.m16n8k16.row.col.f32.bf16.bf16.f32 "
        "{%0,%1,%2,%3}, {%4,%5,%6,%7}, {%8,%9}, {%0,%1,%2,%3};"
        : "+f"(c[0]), "+f"(c[1]), "+f"(c[2]), "+f"(c[3])
        : "r"(a[0]), "r"(a[1]), "r"(a[2]), "r"(a[3]), "r"(b[0]), "r"(b[1]));
}

// ============================================================================
// one-time weight splits (bf16 hi/lo), plain row-major
// ============================================================================
__global__ void __launch_bounds__(256) prep_Wd_kernel(const float* __restrict__ Wd) {
    size_t id = (size_t)blockIdx.x * blockDim.x + threadIdx.x;
    if (id >= (size_t)UD * VD) return;
    __nv_bfloat16 b0, b1;
    split2(Wd[id], b0, b1);
    g_Wd0[id] = b0; g_Wd1[id] = b1;
}
__global__ void __launch_bounds__(256) prep_Wg_kernel(
    const float* __restrict__ Wx, const float* __restrict__ Wh) {
    int id = blockIdx.x * blockDim.x + threadIdx.x;
    if (id >= GK * ZN) return;
    int k = id >> 11, n = id & (ZN - 1);
    float v = (k < UD) ? Wx[(size_t)k * ZN + n] : Wh[(size_t)(k - UD) * ZN + n];
    __nv_bfloat16 b0, b1;
    split2(v, b0, b1);
    g_Wg0[id] = b0; g_Wg1[id] = b1;
}

// ============================================================================
// GATE BODY (device fn): one 64x128 tile of the gate GEMM over K=128.
//   a_src = this thread's 32 fp32 source elements (row tid>>2, col (tid&3)*32)
// ============================================================================
#define FA_ST 272
#define FB_ST 272
#define FSA(spl)      ((spl) * 17408u)
#define FSB(buf, spl) (34816u + ((buf) * 2 + (spl)) * 17408u)
#define FSMEM_G (34816 + 69632)

__device__ __forceinline__ void gate_body(
    unsigned char* smem, uint32_t smb, int tid,
    const float* a_src, int kbase, int zidx, int bx)
{
    const int wid = tid >> 5, lane = tid & 31;
    const int wm = wid & 1, wn = wid >> 1;
    const int n0 = bx * 128;
    const __nv_bfloat16* Bsrc[2] = { g_Wg0, g_Wg1 };

#pragma unroll
    for (int ch = 0; ch < 2; ch++) {
        int kc = kbase + ch * 64;
#pragma unroll
        for (int j = 0; j < 8; j++) {
            int i = tid + j * 256;
            int s = i >> 10, rem = i & 1023, r = rem >> 4, c16 = rem & 15;
            cp16(smb + FSB(ch, s) + r * FB_ST + c16 * 16,
                 Bsrc[s] + (size_t)(kc + r) * ZN + n0 + c16 * 8);
        }
        CP_COMMIT();
    }

    {   // A prep: split2 into smem
        const int row = tid >> 2;
        const int cbase = (tid & 3) * 32;
        __nv_bfloat16* a0 = (__nv_bfloat16*)(smem + FSA(0) + row * FA_ST) + cbase;
        __nv_bfloat16* a1 = (__nv_bfloat16*)(smem + FSA(1) + row * FA_ST) + cbase;
#pragma unroll
        for (int q = 0; q < 8; q++) {
            float4 v = *(const float4*)(a_src + q * 4);
            __nv_bfloat16 lo, hi;
            split2(v.x, lo, hi); a0[q * 4 + 0] = lo; a1[q * 4 + 0] = hi;
            split2(v.y, lo, hi); a0[q * 4 + 1] = lo; a1[q * 4 + 1] = hi;
            split2(v.z, lo, hi); a0[q * 4 + 2] = lo; a1[q * 4 + 2] = hi;
            split2(v.w, lo, hi); a0[q * 4 + 3] = lo; a1[q * 4 + 3] = hi;
        }
    }

    float acc[2][4][4];
#pragma unroll
    for (int i = 0; i < 2; i++)
#pragma unroll
        for (int j = 0; j < 4; j++)
#pragma unroll
            for (int q = 0; q < 4; q++) acc[i][j][q] = 0.f;

#pragma unroll
    for (int ch = 0; ch < 2; ch++) {
        if (ch == 0) { CP_WAIT(1); } else { CP_WAIT(0); }
        __syncthreads();
#pragma unroll
        for (int kf = 0; kf < 4; kf++) {
            uint32_t a0[2][4], a1[2][4];
#pragma unroll
            for (int mf = 0; mf < 2; mf++) {
                uint32_t arow = (wm * 32 + mf * 16 + (lane & 15)) * FA_ST
                              + ch * 128 + kf * 32 + (lane >> 4) * 16;
                ldm_x4(a0[mf], smb + FSA(0) + arow);
                ldm_x4(a1[mf], smb + FSA(1) + arow);
            }
#pragma unroll
            for (int nt = 0; nt < 2; nt++) {
                uint32_t b0[4], b1[4];
                uint32_t boff = (kf * 16 + (lane & 15)) * FB_ST
                              + (wn * 32 + nt * 16) * 2 + (lane >> 4) * 16;
                ldm_x4t(b0, smb + FSB(ch, 0) + boff);
                ldm_x4t(b1, smb + FSB(ch, 1) + boff);
#pragma unroll
                for (int mf = 0; mf < 2; mf++) {
                    mma16816(acc[mf][nt * 2],     a0[mf], b0);
                    mma16816(acc[mf][nt * 2],     a1[mf], b0);
                    mma16816(acc[mf][nt * 2],     a0[mf], b1);
                    mma16816(acc[mf][nt * 2 + 1], a0[mf], b0 + 2);
                    mma16816(acc[mf][nt * 2 + 1], a1[mf], b0 + 2);
                    mma16816(acc[mf][nt * 2 + 1], a0[mf], b1 + 2);
                }
            }
        }
        if (ch == 0) __syncthreads();
    }

    float* zp = g_zpart[zidx];
#pragma unroll
    for (int mf = 0; mf < 2; mf++) {
#pragma unroll
        for (int nti = 0; nti < 4; nti++) {
            int r0 = wm * 32 + mf * 16 + (lane >> 2);
            int col = n0 + wn * 32 + nti * 8 + (lane & 3) * 2;
            *(float2*)&zp[(size_t)r0 * ZN + col] =
                make_float2(acc[mf][nti][0], acc[mf][nti][1]);
            *(float2*)&zp[(size_t)(r0 + 8) * ZN + col] =
                make_float2(acc[mf][nti][2], acc[mf][nti][3]);
        }
    }
}

// ============================================================================
// gate_h0: standalone Wh-half for step 0 (reads h0 input). grid (16,4).
// ============================================================================
__global__ void __launch_bounds__(256, 1) gate_h0_kernel(const float* __restrict__ h0) {
    extern __shared__ unsigned char smem[];
    const uint32_t smb = smem_u32(smem);
    const int tid = threadIdx.x;
    const int bx = blockIdx.x, ky = blockIdx.y;
    const float* a_src = h0 + (tid >> 2) * UD + ky * 128 + (tid & 3) * 32;
    gate_body(smem, smb, tid, a_src, 512 + ky * 128, 4 + ky, bx);
}

// ============================================================================
// STEP FRONT X: emb-half gate GEMM (4 ksplits) + grid barrier(64) + update.
// ============================================================================
__global__ void __launch_bounds__(256, 1) step_front_x_kernel(
    const float* __restrict__ h0, const float* __restrict__ c0,
    const float* __restrict__ emb, const float* __restrict__ b_lstm, int t)
{
    extern __shared__ unsigned char smem[];
    const uint32_t smb = smem_u32(smem);
    const int tid = threadIdx.x;
    const int bx = blockIdx.x, ky = blockIdx.y;

    {
        const int row = tid >> 2;
        int idx = (t == 0) ? 1 : dec_idx(g_amax[row]);
        const float* a_src = emb + (size_t)idx * UD + ky * 128 + (tid & 3) * 32;
        gate_body(smem, smb, tid, a_src, ky * 128, ky, bx);
    }

    // ---- grid barrier over the 64 co-resident blocks ----
    __threadfence();
    __syncthreads();
    if (tid == 0) {
        unsigned int ticket = atomicAdd(&g_barrier, 1u);
        unsigned int target = (ticket / 64u + 1u) * 64u;
        while (*(volatile unsigned int*)&g_barrier < target) __nanosleep(32);
        __threadfence();
    }
    __syncthreads();

    // ---- update: 2 elems per thread (64 blk * 256 thr * 2 = 32768) ----
    {
        int blkLin = blockIdx.y * 16 + blockIdx.x;
        int id = (blkLin * 256 + tid) * 2;
        int b = id >> 9, u = id & 511;
        size_t base = (size_t)b * ZN;
        float2 zi = {0.f, 0.f}, zf = {0.f, 0.f}, zg = {0.f, 0.f}, zo = {0.f, 0.f};
#pragma unroll
        for (int s = 0; s < 8; s++) {
            float2 v;
            v = __ldcg((const float2*)&g_zpart[s][base + u]);        zi.x += v.x; zi.y += v.y;
            v = __ldcg((const float2*)&g_zpart[s][base + 512 + u]);  zf.x += v.x; zf.y += v.y;
            v = __ldcg((const float2*)&g_zpart[s][base + 1024 + u]); zg.x += v.x; zg.y += v.y;
            v = __ldcg((const float2*)&g_zpart[s][base + 1536 + u]); zo.x += v.x; zo.y += v.y;
        }
        float2 bi = *(const float2*)&b_lstm[u];
        float2 bf = *(const float2*)&b_lstm[512 + u];
        float2 bg = *(const float2*)&b_lstm[1024 + u];
        float2 bo = *(const float2*)&b_lstm[1536 + u];
        zi.x += bi.x; zi.y += bi.y; zf.x += bf.x; zf.y += bf.y;
        zg.x += bg.x; zg.y += bg.y; zo.x += bo.x; zo.y += bo.y;

        float2 cp = (t == 0) ? *(const float2*)&c0[id] : *(const float2*)&g_c[id];
        float2 hn, cn;
        {
            float si = 1.f / (1.f + expf(-zi.x));
            float sf = 1.f / (1.f + expf(-zf.x));
            float so = 1.f / (1.f + expf(-zo.x));
            cn.x = sf * cp.x + si * tanhf(zg.x);
            hn.x = so * tanhf(cn.x);
            si = 1.f / (1.f + expf(-zi.y));
            sf = 1.f / (1.f + expf(-zf.y));
            so = 1.f / (1.f + expf(-zo.y));
            cn.y = sf * cp.y + si * tanhf(zg.y);
            hn.y = so * tanhf(cn.y);
        }
        *(float2*)&g_c[id] = cn;
        *(float2*)&g_h[id] = hn;

        __nv_bfloat16 l0, h0b, l1, h1b;
        split2(hn.x, l0, h0b);
        split2(hn.y, l1, h1b);
        __nv_bfloat162 p0; p0.x = l0; p0.y = l1;
        __nv_bfloat162 p1; p1.x = h0b; p1.y = h1b;
        *(__nv_bfloat162*)&g_Al0[id] = p0;
        *(__nv_bfloat162*)&g_Al1[id] = p1;
        if (u == 0) g_amax[b] = 0ull;
    }
}

// ============================================================================
// COMBO: blocks 0-63 = gate Wh-half for step t+1; blocks 64-313 = logits(t).
//   Logits: tile 64x128, 16 K-chunks of 32, 4 stages, ONE sync per chunk,
//   XOR-swizzled B smem (no padding).
// ============================================================================
#define LA_ST 80
#define LSA(st, spl) (((st) * 2 + (spl)) * 5120u)            // 40960 total
#define LSB(st, spl) (40960u + ((st) * 2 + (spl)) * 8192u)   // -> 106496
#define LSAMAX 106496
#define LSMEM  107008

__global__ void __launch_bounds__(256, 2) combo_kernel(
    const float* __restrict__ bd, float* __restrict__ out, int t)
{
    extern __shared__ unsigned char smem[];
    const uint32_t smb = smem_u32(smem);
    const int tid = threadIdx.x;

    if (blockIdx.x < 64) {
        // ---- gate Wh-half for step t+1 (needs only g_h, ready now) ----
        if (t >= TS - 1) return;
        int bx = blockIdx.x & 15, ky = blockIdx.x >> 4;
        const float* a_src = g_h + (tid >> 2) * UD + ky * 128 + (tid & 3) * 32;
        gate_body(smem, smb, tid, a_src, 512 + ky * 128, 4 + ky, bx);
        return;
    }

    // ---- logits ----
    unsigned long long* samax = (unsigned long long*)(smem + LSAMAX);
    const int wid = tid >> 5, lane = tid & 31;
    const int wm = wid & 1, wn = wid >> 1;       // 2 x m32, 4 x n32
    const int nt_raw = (int)blockIdx.x - 64;     // 0..249
    const int nt_idx = (t & 1) ? (249 - nt_raw) : nt_raw;
    const int v0 = nt_idx * 128;

    if (tid < NB) samax[tid] = 0ull;

    const __nv_bfloat16* Asrc[2] = { g_Al0, g_Al1 };
    const __nv_bfloat16* Bsrc[2] = { g_Wd0, g_Wd1 };

    float acc[2][4][4];
#pragma unroll
    for (int i = 0; i < 2; i++)
#pragma unroll
        for (int j = 0; j < 4; j++)
#pragma unroll
            for (int q = 0; q < 4; q++) acc[i][j][q] = 0.f;

    auto load_chunk = [&](int ch, int st) {
        int kc = ch * 32;
        // A: 2 spl * 64 rows * 4 (16B) = 512 ops, 2/thread
#pragma unroll
        for (int j = 0; j < 2; j++) {
            int i = tid + j * 256;
            int s = i >> 8, rem = i & 255, r = rem >> 2, c4 = rem & 3;
            cp16(smb + LSA(st, s) + r * LA_ST + c4 * 16,
                 Asrc[s] + (size_t)r * UD + kc + c4 * 8);
        }
        // B: 2 spl * 32 rows * 16 (16B) = 1024 ops, 4/thread, XOR swizzle
#pragma unroll
        for (int j = 0; j < 4; j++) {
            int i = tid + j * 256;
            int s = i >> 9, rem = i & 511, r = rem >> 4, c16 = rem & 15;
            int sc = c16 ^ ((r & 7) << 1);
            cp16(smb + LSB(st, s) + r * 256 + sc * 16,
                 Bsrc[s] + (size_t)(kc + r) * VD + v0 + c16 * 8);
        }
        CP_COMMIT();
    };

    load_chunk(0, 0);
    load_chunk(1, 1);
    load_chunk(2, 2);

#pragma unroll
    for (int ch = 0; ch < 16; ch++) {
        if (ch < 14)      { CP_WAIT(2); }
        else if (ch == 14){ CP_WAIT(1); }
        else              { CP_WAIT(0); }
        __syncthreads();
        if (ch + 3 < 16) load_chunk(ch + 3, (ch + 3) & 3);  // overwrites stage read at ch-1: safe past sync
        const int st = ch & 3;
#pragma unroll
        for (int kf = 0; kf < 2; kf++) {
            uint32_t a0[2][4], a1[2][4];
#pragma unroll
            for (int mf = 0; mf < 2; mf++) {
                uint32_t arow = (wm * 32 + mf * 16 + (lane & 15)) * LA_ST
                              + kf * 32 + (lane >> 4) * 16;
                ldm_x4(a0[mf], smb + LSA(st, 0) + arow);
                ldm_x4(a1[mf], smb + LSA(st, 1) + arow);
            }
#pragma unroll
            for (int nt = 0; nt < 2; nt++) {
                uint32_t b0[4], b1[4];
                int row = kf * 16 + (lane & 15);
                int c   = wn * 4 + nt * 2 + (lane >> 4);
                uint32_t boff = row * 256 + (uint32_t)(c ^ ((row & 7) << 1)) * 16;
                ldm_x4t(b0, smb + LSB(st, 0) + boff);
                ldm_x4t(b1, smb + LSB(st, 1) + boff);
#pragma unroll
                for (int mf = 0; mf < 2; mf++) {
                    mma16816(acc[mf][nt * 2],     a0[mf], b0);
                    mma16816(acc[mf][nt * 2],     a1[mf], b0);
                    mma16816(acc[mf][nt * 2],     a0[mf], b1);
                    mma16816(acc[mf][nt * 2 + 1], a0[mf], b0 + 2);
                    mma16816(acc[mf][nt * 2 + 1], a1[mf], b0 + 2);
                    mma16816(acc[mf][nt * 2 + 1], a0[mf], b1 + 2);
                }
            }
        }
    }
    __syncthreads();

    // epilogue: bias, streaming store, exact argmax
    unsigned long long best[2][2] = {{0ull, 0ull}, {0ull, 0ull}};
#pragma unroll
    for (int mf = 0; mf < 2; mf++) {
#pragma unroll
        for (int nti = 0; nti < 4; nti++) {
            int r0 = wm * 32 + mf * 16 + (lane >> 2);
            int col = v0 + wn * 32 + nti * 8 + (lane & 3) * 2;
            float2 bb = *(const float2*)&bd[col];
            float2 o0 = make_float2(acc[mf][nti][0] + bb.x, acc[mf][nti][1] + bb.y);
            float2 o1 = make_float2(acc[mf][nti][2] + bb.x, acc[mf][nti][3] + bb.y);
            __stcs((float2*)&out[((size_t)r0 * TS + t) * VD + col], o0);
            __stcs((float2*)&out[((size_t)(r0 + 8) * TS + t) * VD + col], o1);
            unsigned long long e;
            e = enc_max(o0.x, col);     if (e > best[mf][0]) best[mf][0] = e;
            e = enc_max(o0.y, col + 1); if (e > best[mf][0]) best[mf][0] = e;
            e = enc_max(o1.x, col);     if (e > best[mf][1]) best[mf][1] = e;
            e = enc_max(o1.y, col + 1); if (e > best[mf][1]) best[mf][1] = e;
        }
    }
#pragma unroll
    for (int off = 1; off <= 2; off <<= 1) {
#pragma unroll
        for (int mf = 0; mf < 2; mf++)
#pragma unroll
            for (int h = 0; h < 2; h++) {
                unsigned long long o = __shfl_xor_sync(0xFFFFFFFFu, best[mf][h], off);
                if (o > best[mf][h]) best[mf][h] = o;
            }
    }
    if ((lane & 3) == 0) {
#pragma unroll
        for (int mf = 0; mf < 2; mf++)
#pragma unroll
            for (int h = 0; h < 2; h++) {
                int row = wm * 32 + mf * 16 + h * 8 + (lane >> 2);
                atomicMax(&samax[row], best[mf][h]);
            }
    }
    __syncthreads();
    if (tid < NB) atomicMax(&g_amax[tid], samax[tid]);
}

// ============================================================================
extern "C" void kernel_launch(void* const* d_in, const int* in_sizes, int n_in,
                              void* d_out, int out_size) {
    const float* h0  = (const float*)d_in[0];
    const float* c0  = (const float*)d_in[1];
    const float* emb = (const float*)d_in[2];
    const float* Wx  = (const float*)d_in[3];
    const float* Wh  = (const float*)d_in[4];
    const float* bl  = (const float*)d_in[5];
    const float* Wd  = (const float*)d_in[6];
    const float* bd  = (const float*)d_in[7];
    float* out = (float*)d_out;

    static bool attr_done = false;
    if (!attr_done) {
        cudaFuncSetAttribute(gate_h0_kernel,
                             cudaFuncAttributeMaxDynamicSharedMemorySize, FSMEM_G);
        cudaFuncSetAttribute(step_front_x_kernel,
                             cudaFuncAttributeMaxDynamicSharedMemorySize, FSMEM_G);
        cudaFuncSetAttribute(combo_kernel,
                             cudaFuncAttributeMaxDynamicSharedMemorySize, LSMEM);
        attr_done = true;
    }

    prep_Wd_kernel<<<(int)(((size_t)UD * VD + 255) / 256), 256>>>(Wd);
    prep_Wg_kernel<<<(GK * ZN + 255) / 256, 256>>>(Wx, Wh);
    gate_h0_kernel<<<dim3(16, 4), 256, FSMEM_G>>>(h0);   // Wh-half for step 0

    for (int t = 0; t < TS; t++) {
        step_front_x_kernel<<<dim3(16, 4), 256, FSMEM_G>>>(h0, c0, emb, bl, t);
        combo_kernel<<<314, 256, LSMEM>>>(bd, out, t);
    }
}

// round 10
// speedup vs baseline: 1.0985x; 1.0985x over previous
#include <cuda_runtime.h>
#include <cuda_bf16.h>
#include <cstdint>

#define NB 64
#define UD 512
#define VD 32000
#define TS 20
#define ZN 2048
#define GK 1024
#define GKS 8          // gate K-splits (grid.y)

// ---------------- persistent device scratch ----------------
__device__ float g_h[NB * UD];
__device__ float g_c[NB * UD];
__device__ float g_zpart[GKS][NB * ZN];
__device__ unsigned long long g_amax[NB];
__device__ unsigned int g_barrier;   // monotonic ticket barrier (128/launch)
__device__ __nv_bfloat16 g_Wd0[(size_t)UD * VD];
__device__ __nv_bfloat16 g_Wd1[(size_t)UD * VD];
__device__ __nv_bfloat16 g_Wg0[(size_t)GK * ZN];
__device__ __nv_bfloat16 g_Wg1[(size_t)GK * ZN];
__device__ __nv_bfloat16 g_Al0[NB * UD];
__device__ __nv_bfloat16 g_Al1[NB * UD];

// ---------------- helpers ----------------
__device__ __forceinline__ unsigned long long enc_max(float v, int col) {
    unsigned int u = __float_as_uint(v);
    unsigned int key = (u & 0x80000000u) ? ~u : (u | 0x80000000u);
    return ((unsigned long long)key << 32) |
           (unsigned long long)(0xFFFFFFFFu - (unsigned int)col);
}
__device__ __forceinline__ int dec_idx(unsigned long long e) {
    return (int)(0xFFFFFFFFu - (unsigned int)(e & 0xFFFFFFFFull));
}
__device__ __forceinline__ void split2(float v, __nv_bfloat16& b0, __nv_bfloat16& b1) {
    b0 = __float2bfloat16(v);
    b1 = __float2bfloat16(v - __bfloat162float(b0));
}
__device__ __forceinline__ uint32_t smem_u32(const void* p) {
    uint32_t a;
    asm("{ .reg .u64 t; cvta.to.shared.u64 t, %1; cvt.u32.u64 %0, t; }"
        : "=r"(a) : "l"(p));
    return a;
}
__device__ __forceinline__ void cp16(uint32_t dst, const void* src) {
    asm volatile("cp.async.cg.shared.global [%0], [%1], 16;" :: "r"(dst), "l"(src));
}
#define CP_COMMIT() asm volatile("cp.async.commit_group;" ::: "memory")
#define CP_WAIT(n)  asm volatile("cp.async.wait_group %0;" :: "n"(n) : "memory")

__device__ __forceinline__ void ldm_x4(uint32_t* r, uint32_t addr) {
    asm volatile("ldmatrix.sync.aligned.m8n8.x4.shared.b16 {%0,%1,%2,%3}, [%4];"
        : "=r"(r[0]), "=r"(r[1]), "=r"(r[2]), "=r"(r[3]) : "r"(addr));
}
__device__ __forceinline__ void ldm_x4t(uint32_t* r, uint32_t addr) {
    asm volatile("ldmatrix.sync.aligned.m8n8.x4.trans.shared.b16 {%0,%1,%2,%3}, [%4];"
        : "=r"(r[0]), "=r"(r[1]), "=r"(r[2]), "=r"(r[3]) : "r"(addr));
}
__device__ __forceinline__ void mma16816(float* c, const uint32_t* a, const uint32_t* b) {
    asm volatile(
        "mma.sync.aligned.m16n8k16.row.col.f32.bf16.bf16.f32 "
        "{%0,%1,%2,%3}, {%4,%5,%6,%7}, {%8,%9}, {%0,%1,%2,%3};"
        : "+f"(c[0]), "+f"(c[1]), "+f"(c[2]), "+f"(c[3])
        : "r"(a[0]), "r"(a[1]), "r"(a[2]), "r"(a[3]), "r"(b[0]), "r"(b[1]));
}

// ============================================================================
// one-time weight splits (bf16 hi/lo), plain row-major
// ============================================================================
__global__ void __launch_bounds__(256) prep_Wd_kernel(const float* __restrict__ Wd) {
    size_t id = (size_t)blockIdx.x * blockDim.x + threadIdx.x;
    if (id >= (size_t)UD * VD) return;
    __nv_bfloat16 b0, b1;
    split2(Wd[id], b0, b1);
    g_Wd0[id] = b0; g_Wd1[id] = b1;
}
__global__ void __launch_bounds__(256) prep_Wg_kernel(
    const float* __restrict__ Wx, const float* __restrict__ Wh) {
    int id = blockIdx.x * blockDim.x + threadIdx.x;
    if (id >= GK * ZN) return;
    int k = id >> 11, n = id & (ZN - 1);
    float v = (k < UD) ? Wx[(size_t)k * ZN + n] : Wh[(size_t)(k - UD) * ZN + n];
    __nv_bfloat16 b0, b1;
    split2(v, b0, b1);
    g_Wg0[id] = b0; g_Wg1[id] = b1;
}

// ============================================================================
// STEP FRONT: fused gate GEMM + grid barrier + LSTM update. (R8 proven)
//   grid (16 ntiles x 8 ksplits) = 128 blocks, 256 threads.
// ============================================================================
#define FA_ST 272
#define FB_ST 272
#define FSA(spl)      ((spl) * 17408u)
#define FSB(buf, spl) (34816u + ((buf) * 2 + (spl)) * 17408u)
#define FSMEM (34816 + 69632)

__global__ void __launch_bounds__(256, 1) step_front_kernel(
    const float* __restrict__ h0, const float* __restrict__ c0,
    const float* __restrict__ emb, const float* __restrict__ b_lstm, int t)
{
    extern __shared__ unsigned char smem[];
    const uint32_t smb = smem_u32(smem);
    const int tid = threadIdx.x, wid = tid >> 5, lane = tid & 31;
    const int wm = wid & 1, wn = wid >> 1;
    const int n0 = blockIdx.x * 128;
    const int ks = blockIdx.y;
    const int kbase = ks * 128;

    const __nv_bfloat16* Bsrc[2] = { g_Wg0, g_Wg1 };

#pragma unroll
    for (int ch = 0; ch < 2; ch++) {
        int kc = kbase + ch * 64;
#pragma unroll
        for (int j = 0; j < 8; j++) {
            int i = tid + j * 256;
            int s = i >> 10, rem = i & 1023, r = rem >> 4, c16 = rem & 15;
            cp16(smb + FSB(ch, s) + r * FB_ST + c16 * 16,
                 Bsrc[s] + (size_t)(kc + r) * ZN + n0 + c16 * 8);
        }
        CP_COMMIT();
    }

    {
        const int row = tid >> 2;
        const int cbase = (tid & 3) * 32;
        const float* src;
        if (ks < 4) {
            int idx = (t == 0) ? 1 : dec_idx(g_amax[row]);
            src = emb + (size_t)idx * UD + kbase + cbase;
        } else {
            const float* hp = (t == 0) ? h0 : g_h;
            src = hp + row * UD + (ks - 4) * 128 + cbase;
        }
        __nv_bfloat16* a0 = (__nv_bfloat16*)(smem + FSA(0) + row * FA_ST) + cbase;
        __nv_bfloat16* a1 = (__nv_bfloat16*)(smem + FSA(1) + row * FA_ST) + cbase;
#pragma unroll
        for (int q = 0; q < 8; q++) {
            float4 v = *(const float4*)(src + q * 4);
            __nv_bfloat16 lo, hi;
            split2(v.x, lo, hi); a0[q * 4 + 0] = lo; a1[q * 4 + 0] = hi;
            split2(v.y, lo, hi); a0[q * 4 + 1] = lo; a1[q * 4 + 1] = hi;
            split2(v.z, lo, hi); a0[q * 4 + 2] = lo; a1[q * 4 + 2] = hi;
            split2(v.w, lo, hi); a0[q * 4 + 3] = lo; a1[q * 4 + 3] = hi;
        }
    }

    float acc[2][4][4];
#pragma unroll
    for (int i = 0; i < 2; i++)
#pragma unroll
        for (int j = 0; j < 4; j++)
#pragma unroll
            for (int q = 0; q < 4; q++) acc[i][j][q] = 0.f;

#pragma unroll
    for (int ch = 0; ch < 2; ch++) {
        if (ch == 0) { CP_WAIT(1); } else { CP_WAIT(0); }
        __syncthreads();
#pragma unroll
        for (int kf = 0; kf < 4; kf++) {
            uint32_t a0[2][4], a1[2][4];
#pragma unroll
            for (int mf = 0; mf < 2; mf++) {
                uint32_t arow = (wm * 32 + mf * 16 + (lane & 15)) * FA_ST
                              + ch * 128 + kf * 32 + (lane >> 4) * 16;
                ldm_x4(a0[mf], smb + FSA(0) + arow);
                ldm_x4(a1[mf], smb + FSA(1) + arow);
            }
#pragma unroll
            for (int nt = 0; nt < 2; nt++) {
                uint32_t b0[4], b1[4];
                uint32_t boff = (kf * 16 + (lane & 15)) * FB_ST
                              + (wn * 32 + nt * 16) * 2 + (lane >> 4) * 16;
                ldm_x4t(b0, smb + FSB(ch, 0) + boff);
                ldm_x4t(b1, smb + FSB(ch, 1) + boff);
#pragma unroll
                for (int mf = 0; mf < 2; mf++) {
                    mma16816(acc[mf][nt * 2],     a0[mf], b0);
                    mma16816(acc[mf][nt * 2],     a1[mf], b0);
                    mma16816(acc[mf][nt * 2],     a0[mf], b1);
                    mma16816(acc[mf][nt * 2 + 1], a0[mf], b0 + 2);
                    mma16816(acc[mf][nt * 2 + 1], a1[mf], b0 + 2);
                    mma16816(acc[mf][nt * 2 + 1], a0[mf], b1 + 2);
                }
            }
        }
        if (ch == 0) __syncthreads();
    }

    float* zp = g_zpart[ks];
#pragma unroll
    for (int mf = 0; mf < 2; mf++) {
#pragma unroll
        for (int nti = 0; nti < 4; nti++) {
            int r0 = wm * 32 + mf * 16 + (lane >> 2);
            int col = n0 + wn * 32 + nti * 8 + (lane & 3) * 2;
            *(float2*)&zp[(size_t)r0 * ZN + col] =
                make_float2(acc[mf][nti][0], acc[mf][nti][1]);
            *(float2*)&zp[(size_t)(r0 + 8) * ZN + col] =
                make_float2(acc[mf][nti][2], acc[mf][nti][3]);
        }
    }

    __threadfence();
    __syncthreads();
    if (tid == 0) {
        unsigned int ticket = atomicAdd(&g_barrier, 1u);
        unsigned int target = (ticket / 128u + 1u) * 128u;
        while (*(volatile unsigned int*)&g_barrier < target) __nanosleep(32);
        __threadfence();
    }
    __syncthreads();

    {
        int blkLin = blockIdx.y * 16 + blockIdx.x;
        int id = blkLin * 256 + tid;
        int b = id >> 9, u = id & 511;
        size_t base = (size_t)b * ZN;
        float zi = 0.f, zf = 0.f, zg = 0.f, zo = 0.f;
#pragma unroll
        for (int s = 0; s < GKS; s++) {
            zi += __ldcg(&g_zpart[s][base + u]);
            zf += __ldcg(&g_zpart[s][base + 512 + u]);
            zg += __ldcg(&g_zpart[s][base + 1024 + u]);
            zo += __ldcg(&g_zpart[s][base + 1536 + u]);
        }
        zi += b_lstm[u];        zf += b_lstm[512 + u];
        zg += b_lstm[1024 + u]; zo += b_lstm[1536 + u];

        float cp = (t == 0) ? c0[id] : g_c[id];
        float si = 1.f / (1.f + expf(-zi));
        float sf = 1.f / (1.f + expf(-zf));
        float so = 1.f / (1.f + expf(-zo));
        float tg = tanhf(zg);
        float cn = sf * cp + si * tg;
        float hn = so * tanhf(cn);
        g_c[id] = cn;
        g_h[id] = hn;

        __nv_bfloat16 lo, hi;
        split2(hn, lo, hi);
        g_Al0[id] = lo; g_Al1[id] = hi;
        if (u == 0) g_amax[b] = 0ull;
    }
}

// ============================================================================
// LOGITS GEMM (R9-improved mainloop, standalone): grid 250, tile 64x128,
//   16 K-chunks of 32, 4 stages, ONE sync per chunk, XOR-swizzled B smem.
//   Single wave at 2 blocks/SM (250 <= 296).
// ============================================================================
#define LA_ST 80
#define LSA(st, spl) (((st) * 2 + (spl)) * 5120u)            // 40960 total
#define LSB(st, spl) (40960u + ((st) * 2 + (spl)) * 8192u)   // -> 106496
#define LSAMAX 106496
#define LSMEM  107008

__global__ void __launch_bounds__(256, 2) logits_mma_kernel(
    const float* __restrict__ bd, float* __restrict__ out, int t)
{
    extern __shared__ unsigned char smem[];
    const uint32_t smb = smem_u32(smem);
    unsigned long long* samax = (unsigned long long*)(smem + LSAMAX);
    const int tid = threadIdx.x, wid = tid >> 5, lane = tid & 31;
    const int wm = wid & 1, wn = wid >> 1;       // 2 x m32, 4 x n32
    const int nt_idx = (t & 1) ? (249 - (int)blockIdx.x) : (int)blockIdx.x;
    const int v0 = nt_idx * 128;

    if (tid < NB) samax[tid] = 0ull;

    const __nv_bfloat16* Asrc[2] = { g_Al0, g_Al1 };
    const __nv_bfloat16* Bsrc[2] = { g_Wd0, g_Wd1 };

    float acc[2][4][4];
#pragma unroll
    for (int i = 0; i < 2; i++)
#pragma unroll
        for (int j = 0; j < 4; j++)
#pragma unroll
            for (int q = 0; q < 4; q++) acc[i][j][q] = 0.f;

    auto load_chunk = [&](int ch, int st) {
        int kc = ch * 32;
        // A: 2 spl * 64 rows * 4 (16B) = 512 ops, 2/thread
#pragma unroll
        for (int j = 0; j < 2; j++) {
            int i = tid + j * 256;
            int s = i >> 8, rem = i & 255, r = rem >> 2, c4 = rem & 3;
            cp16(smb + LSA(st, s) + r * LA_ST + c4 * 16,
                 Asrc[s] + (size_t)r * UD + kc + c4 * 8);
        }
        // B: 2 spl * 32 rows * 16 (16B) = 1024 ops, 4/thread, XOR swizzle
#pragma unroll
        for (int j = 0; j < 4; j++) {
            int i = tid + j * 256;
            int s = i >> 9, rem = i & 511, r = rem >> 4, c16 = rem & 15;
            int sc = c16 ^ ((r & 7) << 1);
            cp16(smb + LSB(st, s) + r * 256 + sc * 16,
                 Bsrc[s] + (size_t)(kc + r) * VD + v0 + c16 * 8);
        }
        CP_COMMIT();
    };

    load_chunk(0, 0);
    load_chunk(1, 1);
    load_chunk(2, 2);

#pragma unroll
    for (int ch = 0; ch < 16; ch++) {
        if (ch < 14)      { CP_WAIT(2); }
        else if (ch == 14){ CP_WAIT(1); }
        else              { CP_WAIT(0); }
        __syncthreads();
        if (ch + 3 < 16) load_chunk(ch + 3, (ch + 3) & 3);  // stage reuse safe past sync
        const int st = ch & 3;
#pragma unroll
        for (int kf = 0; kf < 2; kf++) {
            uint32_t a0[2][4], a1[2][4];
#pragma unroll
            for (int mf = 0; mf < 2; mf++) {
                uint32_t arow = (wm * 32 + mf * 16 + (lane & 15)) * LA_ST
                              + kf * 32 + (lane >> 4) * 16;
                ldm_x4(a0[mf], smb + LSA(st, 0) + arow);
                ldm_x4(a1[mf], smb + LSA(st, 1) + arow);
            }
#pragma unroll
            for (int nt = 0; nt < 2; nt++) {
                uint32_t b0[4], b1[4];
                int row = kf * 16 + (lane & 15);
                int c   = wn * 4 + nt * 2 + (lane >> 4);
                uint32_t boff = row * 256 + (uint32_t)(c ^ ((row & 7) << 1)) * 16;
                ldm_x4t(b0, smb + LSB(st, 0) + boff);
                ldm_x4t(b1, smb + LSB(st, 1) + boff);
#pragma unroll
                for (int mf = 0; mf < 2; mf++) {
                    mma16816(acc[mf][nt * 2],     a0[mf], b0);
                    mma16816(acc[mf][nt * 2],     a1[mf], b0);
                    mma16816(acc[mf][nt * 2],     a0[mf], b1);
                    mma16816(acc[mf][nt * 2 + 1], a0[mf], b0 + 2);
                    mma16816(acc[mf][nt * 2 + 1], a1[mf], b0 + 2);
                    mma16816(acc[mf][nt * 2 + 1], a0[mf], b1 + 2);
                }
            }
        }
    }
    __syncthreads();

    // epilogue: bias, streaming store, exact argmax
    unsigned long long best[2][2] = {{0ull, 0ull}, {0ull, 0ull}};
#pragma unroll
    for (int mf = 0; mf < 2; mf++) {
#pragma unroll
        for (int nti = 0; nti < 4; nti++) {
            int r0 = wm * 32 + mf * 16 + (lane >> 2);
            int col = v0 + wn * 32 + nti * 8 + (lane & 3) * 2;
            float2 bb = *(const float2*)&bd[col];
            float2 o0 = make_float2(acc[mf][nti][0] + bb.x, acc[mf][nti][1] + bb.y);
            float2 o1 = make_float2(acc[mf][nti][2] + bb.x, acc[mf][nti][3] + bb.y);
            __stcs((float2*)&out[((size_t)r0 * TS + t) * VD + col], o0);
            __stcs((float2*)&out[((size_t)(r0 + 8) * TS + t) * VD + col], o1);
            unsigned long long e;
            e = enc_max(o0.x, col);     if (e > best[mf][0]) best[mf][0] = e;
            e = enc_max(o0.y, col + 1); if (e > best[mf][0]) best[mf][0] = e;
            e = enc_max(o1.x, col);     if (e > best[mf][1]) best[mf][1] = e;
            e = enc_max(o1.y, col + 1); if (e > best[mf][1]) best[mf][1] = e;
        }
    }
#pragma unroll
    for (int off = 1; off <= 2; off <<= 1) {
#pragma unroll
        for (int mf = 0; mf < 2; mf++)
#pragma unroll
            for (int h = 0; h < 2; h++) {
                unsigned long long o = __shfl_xor_sync(0xFFFFFFFFu, best[mf][h], off);
                if (o > best[mf][h]) best[mf][h] = o;
            }
    }
    if ((lane & 3) == 0) {
#pragma unroll
        for (int mf = 0; mf < 2; mf++)
#pragma unroll
            for (int h = 0; h < 2; h++) {
                int row = wm * 32 + mf * 16 + h * 8 + (lane >> 2);
                atomicMax(&samax[row], best[mf][h]);
            }
    }
    __syncthreads();
    if (tid < NB) atomicMax(&g_amax[tid], samax[tid]);
}

// ============================================================================
extern "C" void kernel_launch(void* const* d_in, const int* in_sizes, int n_in,
                              void* d_out, int out_size) {
    const float* h0  = (const float*)d_in[0];
    const float* c0  = (const float*)d_in[1];
    const float* emb = (const float*)d_in[2];
    const float* Wx  = (const float*)d_in[3];
    const float* Wh  = (const float*)d_in[4];
    const float* bl  = (const float*)d_in[5];
    const float* Wd  = (const float*)d_in[6];
    const float* bd  = (const float*)d_in[7];
    float* out = (float*)d_out;

    static bool attr_done = false;
    if (!attr_done) {
        cudaFuncSetAttribute(step_front_kernel,
                             cudaFuncAttributeMaxDynamicSharedMemorySize, FSMEM);
        cudaFuncSetAttribute(logits_mma_kernel,
                             cudaFuncAttributeMaxDynamicSharedMemorySize, LSMEM);
        attr_done = true;
    }

    prep_Wd_kernel<<<(int)(((size_t)UD * VD + 255) / 256), 256>>>(Wd);
    prep_Wg_kernel<<<(GK * ZN + 255) / 256, 256>>>(Wx, Wh);

    for (int t = 0; t < TS; t++) {
        step_front_kernel<<<dim3(16, GKS), 256, FSMEM>>>(h0, c0, emb, bl, t);
        logits_mma_kernel<<<250, 256, LSMEM>>>(bd, out, t);
    }
}

// round 11
// speedup vs baseline: 1.1304x; 1.0290x over previous
#include <cuda_runtime.h>
#include <cuda_bf16.h>
#include <cstdint>

#define NB 64
#define UD 512
#define VD 32000
#define TS 20
#define ZN 2048
#define GK 1024
#define GKS 8          // gate K-splits

// ---------------- persistent device scratch ----------------
__device__ float g_h[NB * UD];
__device__ float g_c[NB * UD];
__device__ float g_zpart[GKS][NB * ZN];
__device__ unsigned long long g_amax[NB];
__device__ unsigned int g_barrier;   // front0 barrier (128/launch)
__device__ unsigned int g_bar1;      // fused barrier1 (250/launch when used)
__device__ unsigned int g_bar2;      // fused barrier2 (128/launch when used)
__device__ __nv_bfloat16 g_Wd0[(size_t)UD * VD];
__device__ __nv_bfloat16 g_Wd1[(size_t)UD * VD];
__device__ __nv_bfloat16 g_Wg0[(size_t)GK * ZN];
__device__ __nv_bfloat16 g_Wg1[(size_t)GK * ZN];
__device__ __nv_bfloat16 g_Al0[NB * UD];
__device__ __nv_bfloat16 g_Al1[NB * UD];

// ---------------- helpers ----------------
__device__ __forceinline__ unsigned long long enc_max(float v, int col) {
    unsigned int u = __float_as_uint(v);
    unsigned int key = (u & 0x80000000u) ? ~u : (u | 0x80000000u);
    return ((unsigned long long)key << 32) |
           (unsigned long long)(0xFFFFFFFFu - (unsigned int)col);
}
__device__ __forceinline__ int dec_idx(unsigned long long e) {
    return (int)(0xFFFFFFFFu - (unsigned int)(e & 0xFFFFFFFFull));
}
__device__ __forceinline__ void split2(float v, __nv_bfloat16& b0, __nv_bfloat16& b1) {
    b0 = __float2bfloat16(v);
    b1 = __float2bfloat16(v - __bfloat162float(b0));
}
__device__ __forceinline__ uint32_t smem_u32(const void* p) {
    uint32_t a;
    asm("{ .reg .u64 t; cvta.to.shared.u64 t, %1; cvt.u32.u64 %0, t; }"
        : "=r"(a) : "l"(p));
    return a;
}
__device__ __forceinline__ void cp16(uint32_t dst, const void* src) {
    asm volatile("cp.async.cg.shared.global [%0], [%1], 16;" :: "r"(dst), "l"(src));
}
#define CP_COMMIT() asm volatile("cp.async.commit_group;" ::: "memory")
#define CP_WAIT(n)  asm volatile("cp.async.wait_group %0;" :: "n"(n) : "memory")

__device__ __forceinline__ void ldm_x4(uint32_t* r, uint32_t addr) {
    asm volatile("ldmatrix.sync.aligned.m8n8.x4.shared.b16 {%0,%1,%2,%3}, [%4];"
        : "=r"(r[0]), "=r"(r[1]), "=r"(r[2]), "=r"(r[3]) : "r"(addr));
}
__device__ __forceinline__ void ldm_x4t(uint32_t* r, uint32_t addr) {
    asm volatile("ldmatrix.sync.aligned.m8n8.x4.trans.shared.b16 {%0,%1,%2,%3}, [%4];"
        : "=r"(r[0]), "=r"(r[1]), "=r"(r[2]), "=r"(r[3]) : "r"(addr));
}
__device__ __forceinline__ void mma16816(float* c, const uint32_t* a, const uint32_t* b) {
    asm volatile(
        "mma.sync.aligned.m16n8k16.row.col.f32.bf16.bf16.f32 "
        "{%0,%1,%2,%3}, {%4,%5,%6,%7}, {%8,%9}, {%0,%1,%2,%3};"
        : "+f"(c[0]), "+f"(c[1]), "+f"(c[2]), "+f"(c[3])
        : "r"(a[0]), "r"(a[1]), "r"(a[2]), "r"(a[3]), "r"(b[0]), "r"(b[1]));
}

// ============================================================================
// one-time weight splits (bf16 hi/lo), plain row-major
// ============================================================================
__global__ void __launch_bounds__(256) prep_Wd_kernel(const float* __restrict__ Wd) {
    size_t id = ((size_t)blockIdx.x * blockDim.x + threadIdx.x) * 4;
    if (id >= (size_t)UD * VD) return;
    float4 v = *(const float4*)&Wd[id];
    __nv_bfloat16 lo[4], hi[4];
    split2(v.x, lo[0], hi[0]);
    split2(v.y, lo[1], hi[1]);
    split2(v.z, lo[2], hi[2]);
    split2(v.w, lo[3], hi[3]);
    *(uint2*)&g_Wd0[id] = *(uint2*)lo;
    *(uint2*)&g_Wd1[id] = *(uint2*)hi;
}
__global__ void __launch_bounds__(256) prep_Wg_kernel(
    const float* __restrict__ Wx, const float* __restrict__ Wh) {
    int id = blockIdx.x * blockDim.x + threadIdx.x;
    if (id >= GK * ZN) return;
    int k = id >> 11, n = id & (ZN - 1);
    float v = (k < UD) ? Wx[(size_t)k * ZN + n] : Wh[(size_t)(k - UD) * ZN + n];
    __nv_bfloat16 b0, b1;
    split2(v, b0, b1);
    g_Wg0[id] = b0; g_Wg1[id] = b1;
}

// ============================================================================
// STEP FRONT (used once, t=0): fused gate GEMM + grid barrier + update.
//   grid (16 ntiles x 8 ksplits) = 128 blocks, 256 threads. (R8/R10 proven)
// ============================================================================
#define FA_ST 272
#define FB_ST 272
#define FSA(spl)      ((spl) * 17408u)
#define FSB(buf, spl) (34816u + ((buf) * 2 + (spl)) * 17408u)
#define FSMEM (34816 + 69632)

__global__ void __launch_bounds__(256, 1) step_front_kernel(
    const float* __restrict__ h0, const float* __restrict__ c0,
    const float* __restrict__ emb, const float* __restrict__ b_lstm)
{
    extern __shared__ unsigned char smem[];
    const uint32_t smb = smem_u32(smem);
    const int tid = threadIdx.x, wid = tid >> 5, lane = tid & 31;
    const int wm = wid & 1, wn = wid >> 1;
    const int n0 = blockIdx.x * 128;
    const int ks = blockIdx.y;
    const int kbase = ks * 128;

    const __nv_bfloat16* Bsrc[2] = { g_Wg0, g_Wg1 };

#pragma unroll
    for (int ch = 0; ch < 2; ch++) {
        int kc = kbase + ch * 64;
#pragma unroll
        for (int j = 0; j < 8; j++) {
            int i = tid + j * 256;
            int s = i >> 10, rem = i & 1023, r = rem >> 4, c16 = rem & 15;
            cp16(smb + FSB(ch, s) + r * FB_ST + c16 * 16,
                 Bsrc[s] + (size_t)(kc + r) * ZN + n0 + c16 * 8);
        }
        CP_COMMIT();
    }

    {
        const int row = tid >> 2;
        const int cbase = (tid & 3) * 32;
        // t == 0: GO token (index 1) for emb half, h0 for h half
        const float* src = (ks < 4)
            ? emb + (size_t)1 * UD + kbase + cbase
            : h0 + row * UD + (ks - 4) * 128 + cbase;
        __nv_bfloat16* a0 = (__nv_bfloat16*)(smem + FSA(0) + row * FA_ST) + cbase;
        __nv_bfloat16* a1 = (__nv_bfloat16*)(smem + FSA(1) + row * FA_ST) + cbase;
#pragma unroll
        for (int q = 0; q < 8; q++) {
            float4 v = *(const float4*)(src + q * 4);
            __nv_bfloat16 lo, hi;
            split2(v.x, lo, hi); a0[q * 4 + 0] = lo; a1[q * 4 + 0] = hi;
            split2(v.y, lo, hi); a0[q * 4 + 1] = lo; a1[q * 4 + 1] = hi;
            split2(v.z, lo, hi); a0[q * 4 + 2] = lo; a1[q * 4 + 2] = hi;
            split2(v.w, lo, hi); a0[q * 4 + 3] = lo; a1[q * 4 + 3] = hi;
        }
    }

    float acc[2][4][4];
#pragma unroll
    for (int i = 0; i < 2; i++)
#pragma unroll
        for (int j = 0; j < 4; j++)
#pragma unroll
            for (int q = 0; q < 4; q++) acc[i][j][q] = 0.f;

#pragma unroll
    for (int ch = 0; ch < 2; ch++) {
        if (ch == 0) { CP_WAIT(1); } else { CP_WAIT(0); }
        __syncthreads();
#pragma unroll
        for (int kf = 0; kf < 4; kf++) {
            uint32_t a0[2][4], a1[2][4];
#pragma unroll
            for (int mf = 0; mf < 2; mf++) {
                uint32_t arow = (wm * 32 + mf * 16 + (lane & 15)) * FA_ST
                              + ch * 128 + kf * 32 + (lane >> 4) * 16;
                ldm_x4(a0[mf], smb + FSA(0) + arow);
                ldm_x4(a1[mf], smb + FSA(1) + arow);
            }
#pragma unroll
            for (int nt = 0; nt < 2; nt++) {
                uint32_t b0[4], b1[4];
                uint32_t boff = (kf * 16 + (lane & 15)) * FB_ST
                              + (wn * 32 + nt * 16) * 2 + (lane >> 4) * 16;
                ldm_x4t(b0, smb + FSB(ch, 0) + boff);
                ldm_x4t(b1, smb + FSB(ch, 1) + boff);
#pragma unroll
                for (int mf = 0; mf < 2; mf++) {
                    mma16816(acc[mf][nt * 2],     a0[mf], b0);
                    mma16816(acc[mf][nt * 2],     a1[mf], b0);
                    mma16816(acc[mf][nt * 2],     a0[mf], b1);
                    mma16816(acc[mf][nt * 2 + 1], a0[mf], b0 + 2);
                    mma16816(acc[mf][nt * 2 + 1], a1[mf], b0 + 2);
                    mma16816(acc[mf][nt * 2 + 1], a0[mf], b1 + 2);
                }
            }
        }
        if (ch == 0) __syncthreads();
    }

    float* zp = g_zpart[ks];
#pragma unroll
    for (int mf = 0; mf < 2; mf++) {
#pragma unroll
        for (int nti = 0; nti < 4; nti++) {
            int r0 = wm * 32 + mf * 16 + (lane >> 2);
            int col = n0 + wn * 32 + nti * 8 + (lane & 3) * 2;
            *(float2*)&zp[(size_t)r0 * ZN + col] =
                make_float2(acc[mf][nti][0], acc[mf][nti][1]);
            *(float2*)&zp[(size_t)(r0 + 8) * ZN + col] =
                make_float2(acc[mf][nti][2], acc[mf][nti][3]);
        }
    }

    __threadfence();
    __syncthreads();
    if (tid == 0) {
        unsigned int ticket = atomicAdd(&g_barrier, 1u);
        unsigned int target = (ticket / 128u + 1u) * 128u;
        while (*(volatile unsigned int*)&g_barrier < target) __nanosleep(32);
        __threadfence();
    }
    __syncthreads();

    {
        int blkLin = blockIdx.y * 16 + blockIdx.x;
        int id = blkLin * 256 + tid;
        int b = id >> 9, u = id & 511;
        size_t base = (size_t)b * ZN;
        float zi = 0.f, zf = 0.f, zg = 0.f, zo = 0.f;
#pragma unroll
        for (int s = 0; s < GKS; s++) {
            zi += __ldcg(&g_zpart[s][base + u]);
            zf += __ldcg(&g_zpart[s][base + 512 + u]);
            zg += __ldcg(&g_zpart[s][base + 1024 + u]);
            zo += __ldcg(&g_zpart[s][base + 1536 + u]);
        }
        zi += b_lstm[u];        zf += b_lstm[512 + u];
        zg += b_lstm[1024 + u]; zo += b_lstm[1536 + u];

        float cp = c0[id];
        float si = 1.f / (1.f + expf(-zi));
        float sf = 1.f / (1.f + expf(-zf));
        float so = 1.f / (1.f + expf(-zo));
        float tg = tanhf(zg);
        float cn = sf * cp + si * tg;
        float hn = so * tanhf(cn);
        g_c[id] = cn;
        g_h[id] = hn;

        __nv_bfloat16 lo, hi;
        split2(hn, lo, hi);
        g_Al0[id] = lo; g_Al1[id] = hi;
        if (u == 0) g_amax[b] = 0ull;
    }
}

// ============================================================================
// FUSED: logits(t) [250 blocks] -> barrier(250) -> gate(t+1)+update [128 blks]
//   Logits mainloop identical to R10 (proven 25.8us). Blocks >=128 exit after
//   barrier1. t == TS-1 skips phases 2-3 entirely.
// ============================================================================
#define LA_ST 80
#define LSA(st, spl) (((st) * 2 + (spl)) * 5120u)            // 40960 total
#define LSB(st, spl) (40960u + ((st) * 2 + (spl)) * 8192u)   // -> 106496
#define LSAMAX 106496
#define LSMEM  107008

__global__ void __launch_bounds__(256, 2) fused_step_kernel(
    const float* __restrict__ bd, float* __restrict__ out,
    const float* __restrict__ emb, const float* __restrict__ b_lstm, int t)
{
    extern __shared__ unsigned char smem[];
    const uint32_t smb = smem_u32(smem);
    unsigned long long* samax = (unsigned long long*)(smem + LSAMAX);
    const int tid = threadIdx.x, wid = tid >> 5, lane = tid & 31;
    const int wm = wid & 1, wn = wid >> 1;       // 2 x m32, 4 x n32
    const int nt_idx = (t & 1) ? (249 - (int)blockIdx.x) : (int)blockIdx.x;
    const int v0 = nt_idx * 128;

    if (tid < NB) samax[tid] = 0ull;

    {   // ================= PHASE 1: logits GEMM (R10 mainloop) =================
        const __nv_bfloat16* Asrc[2] = { g_Al0, g_Al1 };
        const __nv_bfloat16* Bsrc[2] = { g_Wd0, g_Wd1 };

        float acc[2][4][4];
#pragma unroll
        for (int i = 0; i < 2; i++)
#pragma unroll
            for (int j = 0; j < 4; j++)
#pragma unroll
                for (int q = 0; q < 4; q++) acc[i][j][q] = 0.f;

        auto load_chunk = [&](int ch, int st) {
            int kc = ch * 32;
#pragma unroll
            for (int j = 0; j < 2; j++) {
                int i = tid + j * 256;
                int s = i >> 8, rem = i & 255, r = rem >> 2, c4 = rem & 3;
                cp16(smb + LSA(st, s) + r * LA_ST + c4 * 16,
                     Asrc[s] + (size_t)r * UD + kc + c4 * 8);
            }
#pragma unroll
            for (int j = 0; j < 4; j++) {
                int i = tid + j * 256;
                int s = i >> 9, rem = i & 511, r = rem >> 4, c16 = rem & 15;
                int sc = c16 ^ ((r & 7) << 1);
                cp16(smb + LSB(st, s) + r * 256 + sc * 16,
                     Bsrc[s] + (size_t)(kc + r) * VD + v0 + c16 * 8);
            }
            CP_COMMIT();
        };

        load_chunk(0, 0);
        load_chunk(1, 1);
        load_chunk(2, 2);

#pragma unroll
        for (int ch = 0; ch < 16; ch++) {
            if (ch < 14)      { CP_WAIT(2); }
            else if (ch == 14){ CP_WAIT(1); }
            else              { CP_WAIT(0); }
            __syncthreads();
            if (ch + 3 < 16) load_chunk(ch + 3, (ch + 3) & 3);
            const int st = ch & 3;
#pragma unroll
            for (int kf = 0; kf < 2; kf++) {
                uint32_t a0[2][4], a1[2][4];
#pragma unroll
                for (int mf = 0; mf < 2; mf++) {
                    uint32_t arow = (wm * 32 + mf * 16 + (lane & 15)) * LA_ST
                                  + kf * 32 + (lane >> 4) * 16;
                    ldm_x4(a0[mf], smb + LSA(st, 0) + arow);
                    ldm_x4(a1[mf], smb + LSA(st, 1) + arow);
                }
#pragma unroll
                for (int nt = 0; nt < 2; nt++) {
                    uint32_t b0[4], b1[4];
                    int row = kf * 16 + (lane & 15);
                    int c   = wn * 4 + nt * 2 + (lane >> 4);
                    uint32_t boff = row * 256 + (uint32_t)(c ^ ((row & 7) << 1)) * 16;
                    ldm_x4t(b0, smb + LSB(st, 0) + boff);
                    ldm_x4t(b1, smb + LSB(st, 1) + boff);
#pragma unroll
                    for (int mf = 0; mf < 2; mf++) {
                        mma16816(acc[mf][nt * 2],     a0[mf], b0);
                        mma16816(acc[mf][nt * 2],     a1[mf], b0);
                        mma16816(acc[mf][nt * 2],     a0[mf], b1);
                        mma16816(acc[mf][nt * 2 + 1], a0[mf], b0 + 2);
                        mma16816(acc[mf][nt * 2 + 1], a1[mf], b0 + 2);
                        mma16816(acc[mf][nt * 2 + 1], a0[mf], b1 + 2);
                    }
                }
            }
        }
        __syncthreads();

        // epilogue: bias, streaming store, exact argmax
        unsigned long long best[2][2] = {{0ull, 0ull}, {0ull, 0ull}};
#pragma unroll
        for (int mf = 0; mf < 2; mf++) {
#pragma unroll
            for (int nti = 0; nti < 4; nti++) {
                int r0 = wm * 32 + mf * 16 + (lane >> 2);
                int col = v0 + wn * 32 + nti * 8 + (lane & 3) * 2;
                float2 bb = *(const float2*)&bd[col];
                float2 o0 = make_float2(acc[mf][nti][0] + bb.x, acc[mf][nti][1] + bb.y);
                float2 o1 = make_float2(acc[mf][nti][2] + bb.x, acc[mf][nti][3] + bb.y);
                __stcs((float2*)&out[((size_t)r0 * TS + t) * VD + col], o0);
                __stcs((float2*)&out[((size_t)(r0 + 8) * TS + t) * VD + col], o1);
                unsigned long long e;
                e = enc_max(o0.x, col);     if (e > best[mf][0]) best[mf][0] = e;
                e = enc_max(o0.y, col + 1); if (e > best[mf][0]) best[mf][0] = e;
                e = enc_max(o1.x, col);     if (e > best[mf][1]) best[mf][1] = e;
                e = enc_max(o1.y, col + 1); if (e > best[mf][1]) best[mf][1] = e;
            }
        }
#pragma unroll
        for (int off = 1; off <= 2; off <<= 1) {
#pragma unroll
            for (int mf = 0; mf < 2; mf++)
#pragma unroll
                for (int h = 0; h < 2; h++) {
                    unsigned long long o = __shfl_xor_sync(0xFFFFFFFFu, best[mf][h], off);
                    if (o > best[mf][h]) best[mf][h] = o;
                }
        }
        if ((lane & 3) == 0) {
#pragma unroll
            for (int mf = 0; mf < 2; mf++)
#pragma unroll
                for (int h = 0; h < 2; h++) {
                    int row = wm * 32 + mf * 16 + h * 8 + (lane >> 2);
                    atomicMax(&samax[row], best[mf][h]);
                }
        }
        __syncthreads();
        if (tid < NB) atomicMax(&g_amax[tid], samax[tid]);
    }

    if (t == TS - 1) return;   // last step: no gate/update needed

    // ================= BARRIER 1: all 250 blocks =================
    __threadfence();
    __syncthreads();
    if (tid == 0) {
        unsigned int ticket = atomicAdd(&g_bar1, 1u);
        if (blockIdx.x < 128) {   // only gate blocks need to spin
            unsigned int target = (ticket / 250u + 1u) * 250u;
            while (*(volatile unsigned int*)&g_bar1 < target) __nanosleep(32);
            __threadfence();
        }
    }
    if (blockIdx.x >= 128) return;   // non-gate blocks done
    __syncthreads();

    // ================= PHASE 2: gate GEMM for step t+1 =================
    {
        const int bx = blockIdx.x & 15, ks = blockIdx.x >> 4;
        const int n0g = bx * 128;
        const int kbase = ks * 128;
        const __nv_bfloat16* Bsrc[2] = { g_Wg0, g_Wg1 };

#pragma unroll
        for (int ch = 0; ch < 2; ch++) {
            int kc = kbase + ch * 64;
#pragma unroll
            for (int j = 0; j < 8; j++) {
                int i = tid + j * 256;
                int s = i >> 10, rem = i & 1023, r = rem >> 4, c16 = rem & 15;
                cp16(smb + FSB(ch, s) + r * FB_ST + c16 * 16,
                     Bsrc[s] + (size_t)(kc + r) * ZN + n0g + c16 * 8);
            }
            CP_COMMIT();
        }

        {
            const int row = tid >> 2;
            const int cbase = (tid & 3) * 32;
            const float* src;
            if (ks < 4) {
                int idx = dec_idx(g_amax[row]);
                src = emb + (size_t)idx * UD + kbase + cbase;
            } else {
                src = g_h + row * UD + (ks - 4) * 128 + cbase;
            }
            __nv_bfloat16* a0 = (__nv_bfloat16*)(smem + FSA(0) + row * FA_ST) + cbase;
            __nv_bfloat16* a1 = (__nv_bfloat16*)(smem + FSA(1) + row * FA_ST) + cbase;
#pragma unroll
            for (int q = 0; q < 8; q++) {
                float4 v = *(const float4*)(src + q * 4);
                __nv_bfloat16 lo, hi;
                split2(v.x, lo, hi); a0[q * 4 + 0] = lo; a1[q * 4 + 0] = hi;
                split2(v.y, lo, hi); a0[q * 4 + 1] = lo; a1[q * 4 + 1] = hi;
                split2(v.z, lo, hi); a0[q * 4 + 2] = lo; a1[q * 4 + 2] = hi;
                split2(v.w, lo, hi); a0[q * 4 + 3] = lo; a1[q * 4 + 3] = hi;
            }
        }

        float acc[2][4][4];
#pragma unroll
        for (int i = 0; i < 2; i++)
#pragma unroll
            for (int j = 0; j < 4; j++)
#pragma unroll
                for (int q = 0; q < 4; q++) acc[i][j][q] = 0.f;

#pragma unroll
        for (int ch = 0; ch < 2; ch++) {
            if (ch == 0) { CP_WAIT(1); } else { CP_WAIT(0); }
            __syncthreads();
#pragma unroll
            for (int kf = 0; kf < 4; kf++) {
                uint32_t a0[2][4], a1[2][4];
#pragma unroll
                for (int mf = 0; mf < 2; mf++) {
                    uint32_t arow = (wm * 32 + mf * 16 + (lane & 15)) * FA_ST
                                  + ch * 128 + kf * 32 + (lane >> 4) * 16;
                    ldm_x4(a0[mf], smb + FSA(0) + arow);
                    ldm_x4(a1[mf], smb + FSA(1) + arow);
                }
#pragma unroll
                for (int nt = 0; nt < 2; nt++) {
                    uint32_t b0[4], b1[4];
                    uint32_t boff = (kf * 16 + (lane & 15)) * FB_ST
                                  + (wn * 32 + nt * 16) * 2 + (lane >> 4) * 16;
                    ldm_x4t(b0, smb + FSB(ch, 0) + boff);
                    ldm_x4t(b1, smb + FSB(ch, 1) + boff);
#pragma unroll
                    for (int mf = 0; mf < 2; mf++) {
                        mma16816(acc[mf][nt * 2],     a0[mf], b0);
                        mma16816(acc[mf][nt * 2],     a1[mf], b0);
                        mma16816(acc[mf][nt * 2],     a0[mf], b1);
                        mma16816(acc[mf][nt * 2 + 1], a0[mf], b0 + 2);
                        mma16816(acc[mf][nt * 2 + 1], a1[mf], b0 + 2);
                        mma16816(acc[mf][nt * 2 + 1], a0[mf], b1 + 2);
                    }
                }
            }
            if (ch == 0) __syncthreads();
        }

        float* zp = g_zpart[ks];
#pragma unroll
        for (int mf = 0; mf < 2; mf++) {
#pragma unroll
            for (int nti = 0; nti < 4; nti++) {
                int r0 = wm * 32 + mf * 16 + (lane >> 2);
                int col = n0g + wn * 32 + nti * 8 + (lane & 3) * 2;
                *(float2*)&zp[(size_t)r0 * ZN + col] =
                    make_float2(acc[mf][nti][0], acc[mf][nti][1]);
                *(float2*)&zp[(size_t)(r0 + 8) * ZN + col] =
                    make_float2(acc[mf][nti][2], acc[mf][nti][3]);
            }
        }
    }

    // ================= BARRIER 2: the 128 gate blocks =================
    __threadfence();
    __syncthreads();
    if (tid == 0) {
        unsigned int ticket = atomicAdd(&g_bar2, 1u);
        unsigned int target = (ticket / 128u + 1u) * 128u;
        while (*(volatile unsigned int*)&g_bar2 < target) __nanosleep(32);
        __threadfence();
    }
    __syncthreads();

    // ================= PHASE 3: LSTM update -> h_{t+1} =================
    {
        int id = (int)blockIdx.x * 256 + tid;
        int b = id >> 9, u = id & 511;
        size_t base = (size_t)b * ZN;
        float zi = 0.f, zf = 0.f, zg = 0.f, zo = 0.f;
#pragma unroll
        for (int s = 0; s < GKS; s++) {
            zi += __ldcg(&g_zpart[s][base + u]);
            zf += __ldcg(&g_zpart[s][base + 512 + u]);
            zg += __ldcg(&g_zpart[s][base + 1024 + u]);
            zo += __ldcg(&g_zpart[s][base + 1536 + u]);
        }
        zi += b_lstm[u];        zf += b_lstm[512 + u];
        zg += b_lstm[1024 + u]; zo += b_lstm[1536 + u];

        float cp = g_c[id];
        float si = 1.f / (1.f + expf(-zi));
        float sf = 1.f / (1.f + expf(-zf));
        float so = 1.f / (1.f + expf(-zo));
        float tg = tanhf(zg);
        float cn = sf * cp + si * tg;
        float hn = so * tanhf(cn);
        g_c[id] = cn;
        g_h[id] = hn;

        __nv_bfloat16 lo, hi;
        split2(hn, lo, hi);
        g_Al0[id] = lo; g_Al1[id] = hi;
        if (u == 0) g_amax[b] = 0ull;
    }
}

// ============================================================================
extern "C" void kernel_launch(void* const* d_in, const int* in_sizes, int n_in,
                              void* d_out, int out_size) {
    const float* h0  = (const float*)d_in[0];
    const float* c0  = (const float*)d_in[1];
    const float* emb = (const float*)d_in[2];
    const float* Wx  = (const float*)d_in[3];
    const float* Wh  = (const float*)d_in[4];
    const float* bl  = (const float*)d_in[5];
    const float* Wd  = (const float*)d_in[6];
    const float* bd  = (const float*)d_in[7];
    float* out = (float*)d_out;

    static bool attr_done = false;
    if (!attr_done) {
        cudaFuncSetAttribute(step_front_kernel,
                             cudaFuncAttributeMaxDynamicSharedMemorySize, FSMEM);
        cudaFuncSetAttribute(fused_step_kernel,
                             cudaFuncAttributeMaxDynamicSharedMemorySize, LSMEM);
        attr_done = true;
    }

    prep_Wd_kernel<<<(int)(((size_t)UD * VD / 4 + 255) / 256), 256>>>(Wd);
    prep_Wg_kernel<<<(GK * ZN + 255) / 256, 256>>>(Wx, Wh);
    step_front_kernel<<<dim3(16, GKS), 256, FSMEM>>>(h0, c0, emb, bl);

    for (int t = 0; t < TS; t++)
        fused_step_kernel<<<250, 256, LSMEM>>>(bd, out, emb, bl, t);
}

// round 12
// speedup vs baseline: 1.1316x; 1.0010x over previous
#include <cuda_runtime.h>
#include <cuda_bf16.h>
#include <cstdint>

#define NB 64
#define UD 512
#define VD 32000
#define TS 20
#define ZN 2048
#define GK 1024
#define GKS 8          // gate K-splits
#define NTILES 250     // logits n-tiles of 128
#define NCHUNK 16      // logits k-chunks of 32

// ---------------- persistent device scratch ----------------
__device__ float g_h[NB * UD];
__device__ float g_c[NB * UD];
__device__ float g_zpart[GKS][NB * ZN];
__device__ unsigned long long g_amax[NB];
__device__ unsigned int g_barrier;   // front0 barrier (128/launch)
__device__ unsigned int g_bar1;      // fused barrier1 (250/launch when used)
__device__ unsigned int g_bar2;      // fused barrier2 (128/launch when used)
// packed Wd: [tile 250][chunk 16][split 2][8192B swizzled smem image]
__device__ __align__(16) unsigned char g_WdT[(size_t)NTILES * NCHUNK * 2 * 8192];
__device__ __nv_bfloat16 g_Wg0[(size_t)GK * ZN];
__device__ __nv_bfloat16 g_Wg1[(size_t)GK * ZN];
__device__ __nv_bfloat16 g_Al0[NB * UD];
__device__ __nv_bfloat16 g_Al1[NB * UD];

// ---------------- helpers ----------------
__device__ __forceinline__ unsigned long long enc_max(float v, int col) {
    unsigned int u = __float_as_uint(v);
    unsigned int key = (u & 0x80000000u) ? ~u : (u | 0x80000000u);
    return ((unsigned long long)key << 32) |
           (unsigned long long)(0xFFFFFFFFu - (unsigned int)col);
}
__device__ __forceinline__ int dec_idx(unsigned long long e) {
    return (int)(0xFFFFFFFFu - (unsigned int)(e & 0xFFFFFFFFull));
}
__device__ __forceinline__ void split2(float v, __nv_bfloat16& b0, __nv_bfloat16& b1) {
    b0 = __float2bfloat16(v);
    b1 = __float2bfloat16(v - __bfloat162float(b0));
}
__device__ __forceinline__ uint32_t smem_u32(const void* p) {
    uint32_t a;
    asm("{ .reg .u64 t; cvta.to.shared.u64 t, %1; cvt.u32.u64 %0, t; }"
        : "=r"(a) : "l"(p));
    return a;
}
__device__ __forceinline__ void cp16(uint32_t dst, const void* src) {
    asm volatile("cp.async.cg.shared.global [%0], [%1], 16;" :: "r"(dst), "l"(src));
}
#define CP_COMMIT() asm volatile("cp.async.commit_group;" ::: "memory")
#define CP_WAIT(n)  asm volatile("cp.async.wait_group %0;" :: "n"(n) : "memory")

__device__ __forceinline__ void ldm_x4(uint32_t* r, uint32_t addr) {
    asm volatile("ldmatrix.sync.aligned.m8n8.x4.shared.b16 {%0,%1,%2,%3}, [%4];"
        : "=r"(r[0]), "=r"(r[1]), "=r"(r[2]), "=r"(r[3]) : "r"(addr));
}
__device__ __forceinline__ void ldm_x4t(uint32_t* r, uint32_t addr) {
    asm volatile("ldmatrix.sync.aligned.m8n8.x4.trans.shared.b16 {%0,%1,%2,%3}, [%4];"
        : "=r"(r[0]), "=r"(r[1]), "=r"(r[2]), "=r"(r[3]) : "r"(addr));
}
__device__ __forceinline__ void mma16816(float* c, const uint32_t* a, const uint32_t* b) {
    asm volatile(
        "mma.sync.aligned.m16n8k16.row.col.f32.bf16.bf16.f32 "
        "{%0,%1,%2,%3}, {%4,%5,%6,%7}, {%8,%9}, {%0,%1,%2,%3};"
        : "+f"(c[0]), "+f"(c[1]), "+f"(c[2]), "+f"(c[3])
        : "r"(a[0]), "r"(a[1]), "r"(a[2]), "r"(a[3]), "r"(b[0]), "r"(b[1]));
}

// ============================================================================
// one-time: pack Wd into tile/chunk/split-major swizzled-smem-image layout.
//   one thread per (tile, chunk, r, c16) = 16B unit per split.
// ============================================================================
__global__ void __launch_bounds__(256) prep_WdT_kernel(const float* __restrict__ Wd) {
    int id = blockIdx.x * blockDim.x + threadIdx.x;   // 250*16*32*16 = 2,048,000
    if (id >= NTILES * NCHUNK * 32 * 16) return;
    int c16 = id & 15;
    int r   = (id >> 4) & 31;
    int ch  = (id >> 9) & 15;
    int nt  = id >> 13;
    int k = ch * 32 + r;
    int n = nt * 128 + c16 * 8;
    const float* src = Wd + (size_t)k * VD + n;
    float4 v0 = *(const float4*)src;
    float4 v1 = *(const float4*)(src + 4);
    __nv_bfloat16 lo[8], hi[8];
    split2(v0.x, lo[0], hi[0]); split2(v0.y, lo[1], hi[1]);
    split2(v0.z, lo[2], hi[2]); split2(v0.w, lo[3], hi[3]);
    split2(v1.x, lo[4], hi[4]); split2(v1.y, lo[5], hi[5]);
    split2(v1.z, lo[6], hi[6]); split2(v1.w, lo[7], hi[7]);
    uint32_t off = (uint32_t)r * 256 + (uint32_t)(c16 ^ ((r & 7) << 1)) * 16;
    unsigned char* base = g_WdT + ((size_t)(nt * NCHUNK + ch) * 2) * 8192;
    *(uint4*)(base + off)        = *(uint4*)lo;
    *(uint4*)(base + 8192 + off) = *(uint4*)hi;
}

__global__ void __launch_bounds__(256) prep_Wg_kernel(
    const float* __restrict__ Wx, const float* __restrict__ Wh) {
    int id = blockIdx.x * blockDim.x + threadIdx.x;
    if (id >= GK * ZN) return;
    int k = id >> 11, n = id & (ZN - 1);
    float v = (k < UD) ? Wx[(size_t)k * ZN + n] : Wh[(size_t)(k - UD) * ZN + n];
    __nv_bfloat16 b0, b1;
    split2(v, b0, b1);
    g_Wg0[id] = b0; g_Wg1[id] = b1;
}

// ============================================================================
// STEP FRONT (used once, t=0): fused gate GEMM + grid barrier + update.
// ============================================================================
#define FA_ST 272
#define FB_ST 272
#define FSA(spl)      ((spl) * 17408u)
#define FSB(buf, spl) (34816u + ((buf) * 2 + (spl)) * 17408u)
#define FSMEM (34816 + 69632)

__global__ void __launch_bounds__(256, 1) step_front_kernel(
    const float* __restrict__ h0, const float* __restrict__ c0,
    const float* __restrict__ emb, const float* __restrict__ b_lstm)
{
    extern __shared__ unsigned char smem[];
    const uint32_t smb = smem_u32(smem);
    const int tid = threadIdx.x, wid = tid >> 5, lane = tid & 31;
    const int wm = wid & 1, wn = wid >> 1;
    const int n0 = blockIdx.x * 128;
    const int ks = blockIdx.y;
    const int kbase = ks * 128;

    const __nv_bfloat16* Bsrc[2] = { g_Wg0, g_Wg1 };

#pragma unroll
    for (int ch = 0; ch < 2; ch++) {
        int kc = kbase + ch * 64;
#pragma unroll
        for (int j = 0; j < 8; j++) {
            int i = tid + j * 256;
            int s = i >> 10, rem = i & 1023, r = rem >> 4, c16 = rem & 15;
            cp16(smb + FSB(ch, s) + r * FB_ST + c16 * 16,
                 Bsrc[s] + (size_t)(kc + r) * ZN + n0 + c16 * 8);
        }
        CP_COMMIT();
    }

    {
        const int row = tid >> 2;
        const int cbase = (tid & 3) * 32;
        const float* src = (ks < 4)
            ? emb + (size_t)1 * UD + kbase + cbase
            : h0 + row * UD + (ks - 4) * 128 + cbase;
        __nv_bfloat16* a0 = (__nv_bfloat16*)(smem + FSA(0) + row * FA_ST) + cbase;
        __nv_bfloat16* a1 = (__nv_bfloat16*)(smem + FSA(1) + row * FA_ST) + cbase;
#pragma unroll
        for (int q = 0; q < 8; q++) {
            float4 v = *(const float4*)(src + q * 4);
            __nv_bfloat16 lo, hi;
            split2(v.x, lo, hi); a0[q * 4 + 0] = lo; a1[q * 4 + 0] = hi;
            split2(v.y, lo, hi); a0[q * 4 + 1] = lo; a1[q * 4 + 1] = hi;
            split2(v.z, lo, hi); a0[q * 4 + 2] = lo; a1[q * 4 + 2] = hi;
            split2(v.w, lo, hi); a0[q * 4 + 3] = lo; a1[q * 4 + 3] = hi;
        }
    }

    float acc[2][4][4];
#pragma unroll
    for (int i = 0; i < 2; i++)
#pragma unroll
        for (int j = 0; j < 4; j++)
#pragma unroll
            for (int q = 0; q < 4; q++) acc[i][j][q] = 0.f;

#pragma unroll
    for (int ch = 0; ch < 2; ch++) {
        if (ch == 0) { CP_WAIT(1); } else { CP_WAIT(0); }
        __syncthreads();
#pragma unroll
        for (int kf = 0; kf < 4; kf++) {
            uint32_t a0[2][4], a1[2][4];
#pragma unroll
            for (int mf = 0; mf < 2; mf++) {
                uint32_t arow = (wm * 32 + mf * 16 + (lane & 15)) * FA_ST
                              + ch * 128 + kf * 32 + (lane >> 4) * 16;
                ldm_x4(a0[mf], smb + FSA(0) + arow);
                ldm_x4(a1[mf], smb + FSA(1) + arow);
            }
#pragma unroll
            for (int nt = 0; nt < 2; nt++) {
                uint32_t b0[4], b1[4];
                uint32_t boff = (kf * 16 + (lane & 15)) * FB_ST
                              + (wn * 32 + nt * 16) * 2 + (lane >> 4) * 16;
                ldm_x4t(b0, smb + FSB(ch, 0) + boff);
                ldm_x4t(b1, smb + FSB(ch, 1) + boff);
#pragma unroll
                for (int mf = 0; mf < 2; mf++) {
                    mma16816(acc[mf][nt * 2],     a0[mf], b0);
                    mma16816(acc[mf][nt * 2],     a1[mf], b0);
                    mma16816(acc[mf][nt * 2],     a0[mf], b1);
                    mma16816(acc[mf][nt * 2 + 1], a0[mf], b0 + 2);
                    mma16816(acc[mf][nt * 2 + 1], a1[mf], b0 + 2);
                    mma16816(acc[mf][nt * 2 + 1], a0[mf], b1 + 2);
                }
            }
        }
        if (ch == 0) __syncthreads();
    }

    float* zp = g_zpart[ks];
#pragma unroll
    for (int mf = 0; mf < 2; mf++) {
#pragma unroll
        for (int nti = 0; nti < 4; nti++) {
            int r0 = wm * 32 + mf * 16 + (lane >> 2);
            int col = n0 + wn * 32 + nti * 8 + (lane & 3) * 2;
            *(float2*)&zp[(size_t)r0 * ZN + col] =
                make_float2(acc[mf][nti][0], acc[mf][nti][1]);
            *(float2*)&zp[(size_t)(r0 + 8) * ZN + col] =
                make_float2(acc[mf][nti][2], acc[mf][nti][3]);
        }
    }

    __threadfence();
    __syncthreads();
    if (tid == 0) {
        unsigned int ticket = atomicAdd(&g_barrier, 1u);
        unsigned int target = (ticket / 128u + 1u) * 128u;
        while (*(volatile unsigned int*)&g_barrier < target) __nanosleep(32);
        __threadfence();
    }
    __syncthreads();

    {
        int blkLin = blockIdx.y * 16 + blockIdx.x;
        int id = blkLin * 256 + tid;
        int b = id >> 9, u = id & 511;
        size_t base = (size_t)b * ZN;
        float zi = 0.f, zf = 0.f, zg = 0.f, zo = 0.f;
#pragma unroll
        for (int s = 0; s < GKS; s++) {
            zi += __ldcg(&g_zpart[s][base + u]);
            zf += __ldcg(&g_zpart[s][base + 512 + u]);
            zg += __ldcg(&g_zpart[s][base + 1024 + u]);
            zo += __ldcg(&g_zpart[s][base + 1536 + u]);
        }
        zi += b_lstm[u];        zf += b_lstm[512 + u];
        zg += b_lstm[1024 + u]; zo += b_lstm[1536 + u];

        float cp = c0[id];
        float si = 1.f / (1.f + expf(-zi));
        float sf = 1.f / (1.f + expf(-zf));
        float so = 1.f / (1.f + expf(-zo));
        float tg = tanhf(zg);
        float cn = sf * cp + si * tg;
        float hn = so * tanhf(cn);
        g_c[id] = cn;
        g_h[id] = hn;

        __nv_bfloat16 lo, hi;
        split2(hn, lo, hi);
        g_Al0[id] = lo; g_Al1[id] = hi;
        if (u == 0) g_amax[b] = 0ull;
    }
}

// ============================================================================
// FUSED: logits(t) [250 blocks] -> barrier(250) -> gate(t+1)+update [128 blks]
//   Logits B now streamed from packed g_WdT (contiguous 16KB per chunk).
// ============================================================================
#define LA_ST 80
#define LSA(st, spl) (((st) * 2 + (spl)) * 5120u)            // 40960 total
#define LSB(st, spl) (40960u + ((st) * 2 + (spl)) * 8192u)   // -> 106496
#define LSAMAX 106496
#define LSMEM  107008

__global__ void __launch_bounds__(256, 2) fused_step_kernel(
    const float* __restrict__ bd, float* __restrict__ out,
    const float* __restrict__ emb, const float* __restrict__ b_lstm, int t)
{
    extern __shared__ unsigned char smem[];
    const uint32_t smb = smem_u32(smem);
    unsigned long long* samax = (unsigned long long*)(smem + LSAMAX);
    const int tid = threadIdx.x, wid = tid >> 5, lane = tid & 31;
    const int wm = wid & 1, wn = wid >> 1;       // 2 x m32, 4 x n32
    const int nt_idx = (t & 1) ? (249 - (int)blockIdx.x) : (int)blockIdx.x;
    const int v0 = nt_idx * 128;

    if (tid < NB) samax[tid] = 0ull;

    {   // ================= PHASE 1: logits GEMM =================
        const __nv_bfloat16* Asrc[2] = { g_Al0, g_Al1 };
        const unsigned char* wt_base = g_WdT + ((size_t)nt_idx * NCHUNK * 2) * 8192;

        float acc[2][4][4];
#pragma unroll
        for (int i = 0; i < 2; i++)
#pragma unroll
            for (int j = 0; j < 4; j++)
#pragma unroll
                for (int q = 0; q < 4; q++) acc[i][j][q] = 0.f;

        auto load_chunk = [&](int ch, int st) {
            int kc = ch * 32;
            // A: 2 spl * 64 rows * 4 (16B) = 512 ops, 2/thread
#pragma unroll
            for (int j = 0; j < 2; j++) {
                int i = tid + j * 256;
                int s = i >> 8, rem = i & 255, r = rem >> 2, c4 = rem & 3;
                cp16(smb + LSA(st, s) + r * LA_ST + c4 * 16,
                     Asrc[s] + (size_t)r * UD + kc + c4 * 8);
            }
            // B: contiguous 16KB chunk copy (pre-swizzled) — 4 x 16B per thread
            const unsigned char* src = wt_base + ((size_t)ch * 2) * 8192;
#pragma unroll
            for (int j = 0; j < 4; j++) {
                int i = tid + j * 256;               // 0..1023 x 16B
                cp16(smb + LSB(st, 0) + (uint32_t)i * 16, src + (size_t)i * 16);
            }
            CP_COMMIT();
        };

        load_chunk(0, 0);
        load_chunk(1, 1);
        load_chunk(2, 2);

#pragma unroll
        for (int ch = 0; ch < 16; ch++) {
            if (ch < 14)      { CP_WAIT(2); }
            else if (ch == 14){ CP_WAIT(1); }
            else              { CP_WAIT(0); }
            __syncthreads();
            if (ch + 3 < 16) load_chunk(ch + 3, (ch + 3) & 3);
            const int st = ch & 3;
#pragma unroll
            for (int kf = 0; kf < 2; kf++) {
                uint32_t a0[2][4], a1[2][4];
#pragma unroll
                for (int mf = 0; mf < 2; mf++) {
                    uint32_t arow = (wm * 32 + mf * 16 + (lane & 15)) * LA_ST
                                  + kf * 32 + (lane >> 4) * 16;
                    ldm_x4(a0[mf], smb + LSA(st, 0) + arow);
                    ldm_x4(a1[mf], smb + LSA(st, 1) + arow);
                }
#pragma unroll
                for (int nt = 0; nt < 2; nt++) {
                    uint32_t b0[4], b1[4];
                    int row = kf * 16 + (lane & 15);
                    int c   = wn * 4 + nt * 2 + (lane >> 4);
                    uint32_t boff = row * 256 + (uint32_t)(c ^ ((row & 7) << 1)) * 16;
                    ldm_x4t(b0, smb + LSB(st, 0) + boff);
                    ldm_x4t(b1, smb + LSB(st, 1) + boff);
#pragma unroll
                    for (int mf = 0; mf < 2; mf++) {
                        mma16816(acc[mf][nt * 2],     a0[mf], b0);
                        mma16816(acc[mf][nt * 2],     a1[mf], b0);
                        mma16816(acc[mf][nt * 2],     a0[mf], b1);
                        mma16816(acc[mf][nt * 2 + 1], a0[mf], b0 + 2);
                        mma16816(acc[mf][nt * 2 + 1], a1[mf], b0 + 2);
                        mma16816(acc[mf][nt * 2 + 1], a0[mf], b1 + 2);
                    }
                }
            }
        }
        __syncthreads();

        // epilogue: bias, streaming store, exact argmax
        unsigned long long best[2][2] = {{0ull, 0ull}, {0ull, 0ull}};
#pragma unroll
        for (int mf = 0; mf < 2; mf++) {
#pragma unroll
            for (int nti = 0; nti < 4; nti++) {
                int r0 = wm * 32 + mf * 16 + (lane >> 2);
                int col = v0 + wn * 32 + nti * 8 + (lane & 3) * 2;
                float2 bb = *(const float2*)&bd[col];
                float2 o0 = make_float2(acc[mf][nti][0] + bb.x, acc[mf][nti][1] + bb.y);
                float2 o1 = make_float2(acc[mf][nti][2] + bb.x, acc[mf][nti][3] + bb.y);
                __stcs((float2*)&out[((size_t)r0 * TS + t) * VD + col], o0);
                __stcs((float2*)&out[((size_t)(r0 + 8) * TS + t) * VD + col], o1);
                unsigned long long e;
                e = enc_max(o0.x, col);     if (e > best[mf][0]) best[mf][0] = e;
                e = enc_max(o0.y, col + 1); if (e > best[mf][0]) best[mf][0] = e;
                e = enc_max(o1.x, col);     if (e > best[mf][1]) best[mf][1] = e;
                e = enc_max(o1.y, col + 1); if (e > best[mf][1]) best[mf][1] = e;
            }
        }
#pragma unroll
        for (int off = 1; off <= 2; off <<= 1) {
#pragma unroll
            for (int mf = 0; mf < 2; mf++)
#pragma unroll
                for (int h = 0; h < 2; h++) {
                    unsigned long long o = __shfl_xor_sync(0xFFFFFFFFu, best[mf][h], off);
                    if (o > best[mf][h]) best[mf][h] = o;
                }
        }
        if ((lane & 3) == 0) {
#pragma unroll
            for (int mf = 0; mf < 2; mf++)
#pragma unroll
                for (int h = 0; h < 2; h++) {
                    int row = wm * 32 + mf * 16 + h * 8 + (lane >> 2);
                    atomicMax(&samax[row], best[mf][h]);
                }
        }
        __syncthreads();
        if (tid < NB) atomicMax(&g_amax[tid], samax[tid]);
    }

    if (t == TS - 1) return;   // last step: no gate/update needed

    // ================= BARRIER 1: all 250 blocks =================
    __threadfence();
    __syncthreads();
    if (tid == 0) {
        unsigned int ticket = atomicAdd(&g_bar1, 1u);
        if (blockIdx.x < 128) {
            unsigned int target = (ticket / 250u + 1u) * 250u;
            while (*(volatile unsigned int*)&g_bar1 < target) __nanosleep(32);
            __threadfence();
        }
    }
    if (blockIdx.x >= 128) return;
    __syncthreads();

    // ================= PHASE 2: gate GEMM for step t+1 =================
    {
        const int bx = blockIdx.x & 15, ks = blockIdx.x >> 4;
        const int n0g = bx * 128;
        const int kbase = ks * 128;
        const __nv_bfloat16* Bsrc[2] = { g_Wg0, g_Wg1 };

#pragma unroll
        for (int ch = 0; ch < 2; ch++) {
            int kc = kbase + ch * 64;
#pragma unroll
            for (int j = 0; j < 8; j++) {
                int i = tid + j * 256;
                int s = i >> 10, rem = i & 1023, r = rem >> 4, c16 = rem & 15;
                cp16(smb + FSB(ch, s) + r * FB_ST + c16 * 16,
                     Bsrc[s] + (size_t)(kc + r) * ZN + n0g + c16 * 8);
            }
            CP_COMMIT();
        }

        {
            const int row = tid >> 2;
            const int cbase = (tid & 3) * 32;
            const float* src;
            if (ks < 4) {
                int idx = dec_idx(g_amax[row]);
                src = emb + (size_t)idx * UD + kbase + cbase;
            } else {
                src = g_h + row * UD + (ks - 4) * 128 + cbase;
            }
            __nv_bfloat16* a0 = (__nv_bfloat16*)(smem + FSA(0) + row * FA_ST) + cbase;
            __nv_bfloat16* a1 = (__nv_bfloat16*)(smem + FSA(1) + row * FA_ST) + cbase;
#pragma unroll
            for (int q = 0; q < 8; q++) {
                float4 v = *(const float4*)(src + q * 4);
                __nv_bfloat16 lo, hi;
                split2(v.x, lo, hi); a0[q * 4 + 0] = lo; a1[q * 4 + 0] = hi;
                split2(v.y, lo, hi); a0[q * 4 + 1] = lo; a1[q * 4 + 1] = hi;
                split2(v.z, lo, hi); a0[q * 4 + 2] = lo; a1[q * 4 + 2] = hi;
                split2(v.w, lo, hi); a0[q * 4 + 3] = lo; a1[q * 4 + 3] = hi;
            }
        }

        float acc[2][4][4];
#pragma unroll
        for (int i = 0; i < 2; i++)
#pragma unroll
            for (int j = 0; j < 4; j++)
#pragma unroll
                for (int q = 0; q < 4; q++) acc[i][j][q] = 0.f;

#pragma unroll
        for (int ch = 0; ch < 2; ch++) {
            if (ch == 0) { CP_WAIT(1); } else { CP_WAIT(0); }
            __syncthreads();
#pragma unroll
            for (int kf = 0; kf < 4; kf++) {
                uint32_t a0[2][4], a1[2][4];
#pragma unroll
                for (int mf = 0; mf < 2; mf++) {
                    uint32_t arow = (wm * 32 + mf * 16 + (lane & 15)) * FA_ST
                                  + ch * 128 + kf * 32 + (lane >> 4) * 16;
                    ldm_x4(a0[mf], smb + FSA(0) + arow);
                    ldm_x4(a1[mf], smb + FSA(1) + arow);
                }
#pragma unroll
                for (int nt = 0; nt < 2; nt++) {
                    uint32_t b0[4], b1[4];
                    uint32_t boff = (kf * 16 + (lane & 15)) * FB_ST
                                  + (wn * 32 + nt * 16) * 2 + (lane >> 4) * 16;
                    ldm_x4t(b0, smb + FSB(ch, 0) + boff);
                    ldm_x4t(b1, smb + FSB(ch, 1) + boff);
#pragma unroll
                    for (int mf = 0; mf < 2; mf++) {
                        mma16816(acc[mf][nt * 2],     a0[mf], b0);
                        mma16816(acc[mf][nt * 2],     a1[mf], b0);
                        mma16816(acc[mf][nt * 2],     a0[mf], b1);
                        mma16816(acc[mf][nt * 2 + 1], a0[mf], b0 + 2);
                        mma16816(acc[mf][nt * 2 + 1], a1[mf], b0 + 2);
                        mma16816(acc[mf][nt * 2 + 1], a0[mf], b1 + 2);
                    }
                }
            }
            if (ch == 0) __syncthreads();
        }

        float* zp = g_zpart[ks];
#pragma unroll
        for (int mf = 0; mf < 2; mf++) {
#pragma unroll
            for (int nti = 0; nti < 4; nti++) {
                int r0 = wm * 32 + mf * 16 + (lane >> 2);
                int col = n0g + wn * 32 + nti * 8 + (lane & 3) * 2;
                *(float2*)&zp[(size_t)r0 * ZN + col] =
                    make_float2(acc[mf][nti][0], acc[mf][nti][1]);
                *(float2*)&zp[(size_t)(r0 + 8) * ZN + col] =
                    make_float2(acc[mf][nti][2], acc[mf][nti][3]);
            }
        }
    }

    // ================= BARRIER 2: the 128 gate blocks =================
    __threadfence();
    __syncthreads();
    if (tid == 0) {
        unsigned int ticket = atomicAdd(&g_bar2, 1u);
        unsigned int target = (ticket / 128u + 1u) * 128u;
        while (*(volatile unsigned int*)&g_bar2 < target) __nanosleep(32);
        __threadfence();
    }
    __syncthreads();

    // ================= PHASE 3: LSTM update -> h_{t+1} =================
    {
        int id = (int)blockIdx.x * 256 + tid;
        int b = id >> 9, u = id & 511;
        size_t base = (size_t)b * ZN;
        float zi = 0.f, zf = 0.f, zg = 0.f, zo = 0.f;
#pragma unroll
        for (int s = 0; s < GKS; s++) {
            zi += __ldcg(&g_zpart[s][base + u]);
            zf += __ldcg(&g_zpart[s][base + 512 + u]);
            zg += __ldcg(&g_zpart[s][base + 1024 + u]);
            zo += __ldcg(&g_zpart[s][base + 1536 + u]);
        }
        zi += b_lstm[u];        zf += b_lstm[512 + u];
        zg += b_lstm[1024 + u]; zo += b_lstm[1536 + u];

        float cp = g_c[id];
        float si = 1.f / (1.f + expf(-zi));
        float sf = 1.f / (1.f + expf(-zf));
        float so = 1.f / (1.f + expf(-zo));
        float tg = tanhf(zg);
        float cn = sf * cp + si * tg;
        float hn = so * tanhf(cn);
        g_c[id] = cn;
        g_h[id] = hn;

        __nv_bfloat16 lo, hi;
        split2(hn, lo, hi);
        g_Al0[id] = lo; g_Al1[id] = hi;
        if (u == 0) g_amax[b] = 0ull;
    }
}

// ============================================================================
extern "C" void kernel_launch(void* const* d_in, const int* in_sizes, int n_in,
                              void* d_out, int out_size) {
    const float* h0  = (const float*)d_in[0];
    const float* c0  = (const float*)d_in[1];
    const float* emb = (const float*)d_in[2];
    const float* Wx  = (const float*)d_in[3];
    const float* Wh  = (const float*)d_in[4];
    const float* bl  = (const float*)d_in[5];
    const float* Wd  = (const float*)d_in[6];
    const float* bd  = (const float*)d_in[7];
    float* out = (float*)d_out;

    static bool attr_done = false;
    if (!attr_done) {
        cudaFuncSetAttribute(step_front_kernel,
                             cudaFuncAttributeMaxDynamicSharedMemorySize, FSMEM);
        cudaFuncSetAttribute(fused_step_kernel,
                             cudaFuncAttributeMaxDynamicSharedMemorySize, LSMEM);
        attr_done = true;
    }

    prep_WdT_kernel<<<(NTILES * NCHUNK * 32 * 16 + 255) / 256, 256>>>(Wd);
    prep_Wg_kernel<<<(GK * ZN + 255) / 256, 256>>>(Wx, Wh);
    step_front_kernel<<<dim3(16, GKS), 256, FSMEM>>>(h0, c0, emb, bl);

    for (int t = 0; t < TS; t++)
        fused_step_kernel<<<250, 256, LSMEM>>>(bd, out, emb, bl, t);
}